// round 17
// baseline (speedup 1.0000x reference)
#include <cuda_runtime.h>
#include <cuda_bf16.h>
#include <cstdint>

#define Bn      4096
#define Dn      256
#define NEXP    4
#define NPAIR   6
#define TM      64
#define TN      64
#define KC      32
#define SPLITK  3
#define NTILE   16
#define NLT     (NPAIR * NTILE)          // 96
#define SPAD    72
#define STG     4
#define NCHC    128                      // conv chunks per expert (32 rows each)
#define CSTRIDE (NLT * TM * TN)          // 393216 floats per slab
#define SQBLK   96

// -------- scratch ---------------------------------------------------------
__device__ float          g_partMean[NEXP * NCHC * Dn];
__device__ __nv_bfloat16  g_z[NEXP * Bn * Dn];
__device__ float          g_partC[(size_t)SPLITK * CSTRIDE];   // 4.7MB
__device__ float          g_bsum[SQBLK];
__device__ unsigned       g_cnt;

__constant__ int c_pi[NPAIR] = {0, 0, 0, 1, 1, 2};
__constant__ int c_pj[NPAIR] = {1, 2, 3, 2, 3, 3};
__constant__ int c_kbase[SPLITK] = {0, 44, 86};
__constant__ int c_kcnt[SPLITK]  = {44, 42, 42};

// -------- kernel 1: fp32->bf16 convert + column partial sums --------------
// grid (NCHC, NEXP) = 512 blocks, 256 threads; 32 rows x 256 cols per block.
// 8 LDG.128 + 4 STG.128 per thread (best-measured conv variant: 6.98us).
__global__ __launch_bounds__(256, 2)
void conv_colsum_kernel(const float* __restrict__ e0,
                        const float* __restrict__ e1,
                        const float* __restrict__ e2,
                        const float* __restrict__ e3) {
    if (blockIdx.x == 0 && blockIdx.y == 0 && threadIdx.x == 0) g_cnt = 0;
    int e  = blockIdx.y;
    int ch = blockIdx.x;
    const float* E = (e == 0) ? e0 : (e == 1) ? e1 : (e == 2) ? e2 : e3;
    int t  = threadIdx.x;
    int f8 = t & 31;              // feature block (8 floats)
    int rg = t >> 5;              // row group (4 rows)

    const float4* src = (const float4*)(E + (size_t)(ch * 32 + rg * 4) * Dn) + f8 * 2;
    uint4* dst = (uint4*)(g_z + ((size_t)e * Bn + ch * 32 + rg * 4) * Dn) + f8;

    float4 va[4], vb[4];
#pragma unroll
    for (int r = 0; r < 4; r++) { va[r] = src[r * 64]; vb[r] = src[r * 64 + 1]; }

    float s[8] = {};
#pragma unroll
    for (int r = 0; r < 4; r++) {
        s[0] += va[r].x; s[1] += va[r].y; s[2] += va[r].z; s[3] += va[r].w;
        s[4] += vb[r].x; s[5] += vb[r].y; s[6] += vb[r].z; s[7] += vb[r].w;
        __nv_bfloat162 p0 = __floats2bfloat162_rn(va[r].x, va[r].y);
        __nv_bfloat162 p1 = __floats2bfloat162_rn(va[r].z, va[r].w);
        __nv_bfloat162 p2 = __floats2bfloat162_rn(vb[r].x, vb[r].y);
        __nv_bfloat162 p3 = __floats2bfloat162_rn(vb[r].z, vb[r].w);
        dst[r * 32] = make_uint4(*(unsigned*)&p0, *(unsigned*)&p1,
                                 *(unsigned*)&p2, *(unsigned*)&p3);
    }
    __shared__ float sm[8][256];
#pragma unroll
    for (int i = 0; i < 8; i++) sm[rg][f8 * 8 + i] = s[i];
    __syncthreads();
    {
        float tot = 0.0f;
#pragma unroll
        for (int g = 0; g < 8; g++) tot += sm[g][t];
        g_partMean[(e * NCHC + ch) * Dn + t] = tot;
    }
}

// -------- HMMA helpers ----------------------------------------------------
__device__ __forceinline__ void cpa16(const void* smem, const void* g) {
    unsigned s = (unsigned)__cvta_generic_to_shared(smem);
    asm volatile("cp.async.cg.shared.global [%0], [%1], 16;\n" :: "r"(s), "l"(g));
}
__device__ __forceinline__ void cp_commit() {
    asm volatile("cp.async.commit_group;\n");
}
__device__ __forceinline__ void cp_wait2() {
    asm volatile("cp.async.wait_group 2;\n");
}
__device__ __forceinline__ void cp_wait0() {
    asm volatile("cp.async.wait_group 0;\n");
}
__device__ __forceinline__ void ldm_x4t(unsigned* r, const void* p) {
    unsigned a = (unsigned)__cvta_generic_to_shared(p);
    asm volatile("ldmatrix.sync.aligned.m8n8.x4.trans.shared.b16 "
                 "{%0,%1,%2,%3}, [%4];"
                 : "=r"(r[0]), "=r"(r[1]), "=r"(r[2]), "=r"(r[3]) : "r"(a));
}
__device__ __forceinline__ void mma16816(float* c, const unsigned* a,
                                         unsigned b0, unsigned b1) {
    asm volatile("mma.sync.aligned.m16n8k16.row.col.f32.bf16.bf16.f32 "
                 "{%0,%1,%2,%3},{%4,%5,%6,%7},{%8,%9},{%0,%1,%2,%3};"
                 : "+f"(c[0]), "+f"(c[1]), "+f"(c[2]), "+f"(c[3])
                 : "r"(a[0]), "r"(a[1]), "r"(a[2]), "r"(a[3]), "r"(b0), "r"(b1));
}

// -------- kernel 2: 64x64 HMMA GEMM, split-K=3 (R7 champion) --------------
__global__ __launch_bounds__(256, 2)
void gemm_kernel() {
    __shared__ __align__(16) __nv_bfloat16 SA[STG][KC][SPAD];
    __shared__ __align__(16) __nv_bfloat16 SB[STG][KC][SPAD];
    __shared__ __nv_bfloat16 tailA[TM], tailB[TN];

    int tile = blockIdx.x;
    int pair = blockIdx.y;
    int slab = blockIdx.z;
    int lt   = pair * NTILE + tile;
    int tm = (tile >> 2) * TM;
    int tn = (tile & 3) * TN;
    int pi = c_pi[pair], pj = c_pj[pair];
    int kbase = c_kbase[slab], kcnt = c_kcnt[slab];
    const __nv_bfloat16* A = g_z + (size_t)pi * Bn * Dn + (size_t)kbase * KC * Dn + tm;
    const __nv_bfloat16* B = g_z + (size_t)pj * Bn * Dn + (size_t)kbase * KC * Dn + tn;

    int t    = threadIdx.x;
    int lane = t & 31;
    int w    = t >> 5;
    int wm   = (w & 3) * 16;
    int wn   = (w >> 2) * 32;

    int lk   = t >> 3;
    int lseg = (t & 7) * 8;
    size_t loff = (size_t)lk * Dn + lseg;

    int grp = lane >> 3, r = lane & 7;
    int aRow = ((grp & 2) ? 8 : 0) + r,  aCol = wm + ((grp & 1) ? 8 : 0);
    int bRow = ((grp & 1) ? 8 : 0) + r;
    int bCol0 = wn +      ((grp & 2) ? 8 : 0);
    int bCol1 = wn + 16 + ((grp & 2) ? 8 : 0);

    float acc[4][4] = {};

    auto issue = [&](int c) {
        if (c < kcnt) {
            int st = c & 3;
            cpa16(&SA[st][lk][lseg], A + (size_t)c * KC * Dn + loff);
            cpa16(&SB[st][lk][lseg], B + (size_t)c * KC * Dn + loff);
        }
        cp_commit();
    };

    issue(0); issue(1); issue(2);

    if (slab == 0) {
        if (t < TM) {
            float s = 0.0f;
#pragma unroll 16
            for (int c = 0; c < NCHC; c++) s += g_partMean[(pi * NCHC + c) * Dn + tm + t];
            tailA[t] = __float2bfloat16(-64.0f * (s * (1.0f / (float)Bn)));
        } else if (t < TM + TN) {
            int tt = t - TM;
            float s = 0.0f;
#pragma unroll 16
            for (int c = 0; c < NCHC; c++) s += g_partMean[(pj * NCHC + c) * Dn + tn + tt];
            tailB[tt] = __float2bfloat16(64.0f * (s * (1.0f / (float)Bn)));
        }
    }

    for (int c = 0; c < kcnt; ++c) {
        cp_wait2();
        __syncthreads();
        issue(c + 3);

        int st = c & 3;
#pragma unroll
        for (int s = 0; s < 2; ++s) {
            int k0 = s * 16;
            unsigned A0[4], B0[4], B1[4];
            ldm_x4t(A0, &SA[st][k0 + aRow][aCol]);
            ldm_x4t(B0, &SB[st][k0 + bRow][bCol0]);
            ldm_x4t(B1, &SB[st][k0 + bRow][bCol1]);
            mma16816(acc[0], A0, B0[0], B0[1]);
            mma16816(acc[1], A0, B0[2], B0[3]);
            mma16816(acc[2], A0, B1[0], B1[1]);
            mma16816(acc[3], A0, B1[2], B1[3]);
        }
    }

    if (slab == 0) {
        cp_wait0();
        __syncthreads();
        {
            int trow = t >> 4;
            int tcol = (t & 15) * 4;
            __nv_bfloat16 z = __float2bfloat16(0.0f);
            __nv_bfloat16 a0 = z, a1 = z, a2 = z, a3 = z;
            __nv_bfloat16 b0 = z, b1 = z, b2 = z, b3 = z;
            if (trow == 0) {
                a0 = tailA[tcol];     a1 = tailA[tcol + 1];
                a2 = tailA[tcol + 2]; a3 = tailA[tcol + 3];
                b0 = tailB[tcol];     b1 = tailB[tcol + 1];
                b2 = tailB[tcol + 2]; b3 = tailB[tcol + 3];
            }
            SA[0][trow][tcol] = a0; SA[0][trow][tcol + 1] = a1;
            SA[0][trow][tcol + 2] = a2; SA[0][trow][tcol + 3] = a3;
            SB[0][trow][tcol] = b0; SB[0][trow][tcol + 1] = b1;
            SB[0][trow][tcol + 2] = b2; SB[0][trow][tcol + 3] = b3;
        }
        __syncthreads();
        {
            unsigned A0[4], B0[4], B1[4];
            ldm_x4t(A0, &SA[0][aRow][aCol]);
            ldm_x4t(B0, &SB[0][bRow][bCol0]);
            ldm_x4t(B1, &SB[0][bRow][bCol1]);
            mma16816(acc[0], A0, B0[0], B0[1]);
            mma16816(acc[1], A0, B0[2], B0[3]);
            mma16816(acc[2], A0, B1[0], B1[1]);
            mma16816(acc[3], A0, B1[2], B1[3]);
        }
    }

    {
        float4* dst4 = (float4*)(g_partC + (size_t)slab * CSTRIDE + ((size_t)lt << 12));
#pragma unroll
        for (int j = 0; j < 4; ++j)
            dst4[j * 256 + t] = make_float4(acc[j][0], acc[j][1], acc[j][2], acc[j][3]);
    }
}

// -------- kernel 3: combine 3 slabs, square, fused final ------------------
// 96 blocks x 256 threads; 16 float4 per thread, deep load batching.
__global__ void sq_kernel(float* __restrict__ out) {
    __shared__ float red[256];
    __shared__ int s_last;
    int t = threadIdx.x;
    const float4* pc = (const float4*)g_partC;
    const int S4 = CSTRIDE / 4;
    int idx0 = blockIdx.x * 1024 + t;
    float s = 0.0f;
#pragma unroll
    for (int u = 0; u < 4; u++) {
        int idx = idx0 + u * 256;
        float4 a = pc[idx], b = pc[S4 + idx], c = pc[2 * S4 + idx];
        float vx = a.x + b.x + c.x;
        float vy = a.y + b.y + c.y;
        float vz = a.z + b.z + c.z;
        float vw = a.w + b.w + c.w;
        s += vx * vx + vy * vy + vz * vz + vw * vw;
    }
#pragma unroll
    for (int o = 16; o > 0; o >>= 1) s += __shfl_xor_sync(0xffffffffu, s, o);
    if ((t & 31) == 0) red[t >> 5] = s;
    __syncthreads();
    if (t == 0) {
        float tot = 0.0f;
#pragma unroll
        for (int i = 0; i < 8; ++i) tot += red[i];
        g_bsum[blockIdx.x] = tot;
        __threadfence();
        unsigned tk = atomicAdd(&g_cnt, 1u);
        s_last = (tk == SQBLK - 1) ? 1 : 0;
    }
    __syncthreads();

    if (s_last) {
        __threadfence();
        red[t] = (t < SQBLK) ? g_bsum[t] : 0.0f;
        __syncthreads();
#pragma unroll
        for (int o = 128; o > 0; o >>= 1) {
            if (t < o) red[t] += red[t + o];
            __syncthreads();
        }
        if (t == 0) {
            const float denom = 4095.0f * 4095.0f;
            out[0] = 0.1f * (red[0] / denom) * (1.0f / (float)NPAIR);
        }
    }
}

// -------- launch ----------------------------------------------------------
extern "C" void kernel_launch(void* const* d_in, const int* in_sizes, int n_in,
                              void* d_out, int out_size) {
    const float* e0 = (const float*)d_in[0];
    const float* e1 = (const float*)d_in[1];
    const float* e2 = (const float*)d_in[2];
    const float* e3 = (const float*)d_in[3];
    float* out = (float*)d_out;

    conv_colsum_kernel<<<dim3(NCHC, NEXP), 256>>>(e0, e1, e2, e3);
    gemm_kernel<<<dim3(NTILE, NPAIR, SPLITK), 256>>>();
    sq_kernel<<<SQBLK, 256>>>(out);
}